// round 6
// baseline (speedup 1.0000x reference)
#include <cuda_runtime.h>
#include <cuda_bf16.h>
#include <cstdint>
#include <cstddef>

// Problem constants
#define SEQ    512
#define BATCH  64
#define UNITS  512
#define GATES  2048          // 4*UNITS, Keras order i,f,g,o

// -------------------- device scratch (no cudaMalloc allowed) --------------------
__device__ float g_xpre[(size_t)SEQ * BATCH * GATES];        // [t][b][gate_col]
__device__ __nv_bfloat16 g_hh[2][BATCH * UNITS];             // h hi, double buffered
__device__ __nv_bfloat16 g_hl[2][BATCH * UNITS];             // h lo
__device__ unsigned g_barr_arrive[4][32];                    // [pg*2+chain], line-padded
__device__ unsigned g_barr_release[4][32];

// -------------------- helpers --------------------
__device__ __forceinline__ uint32_t f32_to_tf32(float x) {
    uint32_t r; asm("cvt.rna.tf32.f32 %0, %1;" : "=r"(r) : "f"(x)); return r;
}

__device__ __forceinline__ void mma_tf32(float c[4],
                                         uint32_t a0, uint32_t a1, uint32_t a2, uint32_t a3,
                                         uint32_t b0, uint32_t b1) {
    asm volatile(
        "mma.sync.aligned.m16n8k8.row.col.f32.tf32.tf32.f32 "
        "{%0,%1,%2,%3}, {%4,%5,%6,%7}, {%8,%9}, {%0,%1,%2,%3};"
        : "+f"(c[0]), "+f"(c[1]), "+f"(c[2]), "+f"(c[3])
        : "r"(a0), "r"(a1), "r"(a2), "r"(a3), "r"(b0), "r"(b1));
}

__device__ __forceinline__ void mma_bf16(float c[4],
                                         uint32_t a0, uint32_t a1, uint32_t a2, uint32_t a3,
                                         uint32_t b0, uint32_t b1) {
    asm volatile(
        "mma.sync.aligned.m16n8k16.row.col.f32.bf16.bf16.f32 "
        "{%0,%1,%2,%3}, {%4,%5,%6,%7}, {%8,%9}, {%0,%1,%2,%3};"
        : "+f"(c[0]), "+f"(c[1]), "+f"(c[2]), "+f"(c[3])
        : "r"(a0), "r"(a1), "r"(a2), "r"(a3), "r"(b0), "r"(b1));
}

__device__ __forceinline__ uint32_t packbf(__nv_bfloat16 lo, __nv_bfloat16 hi) {
    __nv_bfloat162 p = __halves2bfloat162(lo, hi);   // .x = low 16 bits (even k)
    return *(uint32_t*)&p;
}

__device__ __forceinline__ float sigmoid_f(float x) {
    return 1.0f / (1.0f + __expf(-x));
}
__device__ __forceinline__ float tanh_f(float x) {
    float e = __expf(-2.0f * fabsf(x));
    float t = (1.0f - e) / (1.0f + e);
    return copysignf(t, x);
}

// Split barrier over 32 CTAs, monotonic (graph-replay safe).
// arrive: returns the release target for the matching wait.
__device__ __forceinline__ unsigned bar_arrive(int id) {
    unsigned tk = atomicAdd(&g_barr_arrive[id][0], 1u);
    if ((tk & 31u) == 31u) atomicAdd(&g_barr_release[id][0], 1u);
    return (tk >> 5) + 1u;
}
__device__ __forceinline__ void bar_wait(int id, unsigned target) {
    while ((int)(*(volatile unsigned*)&g_barr_release[id][0] - target) < 0) { }
}

// -------------------- kernel 1: Xpre = x @ Wx + bias (mma.sync tf32) --------------------
// Output layout: time-major g_xpre[t][b][col]. Register-prefetch double buffer.
#define A_PITCH 36
#define B_PITCH 136

__global__ __launch_bounds__(256, 2) void xpre_mma(
    const float* __restrict__ X,     // [32768, 512] rows m = b*512 + t
    const float* __restrict__ Wx,    // [512, 2048]
    const float* __restrict__ bias)  // [2048]
{
    __shared__ uint32_t sA[128 * A_PITCH];   // 18 KB
    __shared__ uint32_t sB[32 * B_PITCH];    // 17.4 KB

    const int tid  = threadIdx.x;
    const int lane = tid & 31;
    const int wid  = tid >> 5;
    const int m0 = blockIdx.y << 7;
    const int n0 = blockIdx.x << 7;
    const int wr = wid >> 1;
    const int wc = wid & 1;
    const int gid = lane >> 2;
    const int tig = lane & 3;

    // per-thread load coordinates (4 float4 each for A and B)
    int a_row[4], a_c4[4], b_k[4], b_c4[4];
#pragma unroll
    for (int it = 0; it < 4; it++) {
        int idx = tid + (it << 8);
        a_row[it] = idx >> 3;
        a_c4[it]  = (idx & 7) << 2;
        b_k[it]   = idx >> 5;
        b_c4[it]  = (idx & 31) << 2;
    }

    float acc[2][8][4];
#pragma unroll
    for (int mf = 0; mf < 2; mf++)
#pragma unroll
        for (int nf = 0; nf < 8; nf++)
#pragma unroll
            for (int q = 0; q < 4; q++) acc[mf][nf][q] = 0.0f;

    // prologue: prefetch chunk 0
    float4 pa[4], pb[4];
#pragma unroll
    for (int it = 0; it < 4; it++) {
        pa[it] = *(const float4*)(X + (size_t)(m0 + a_row[it]) * 512 + a_c4[it]);
        pb[it] = *(const float4*)(Wx + (size_t)b_k[it] * 2048 + n0 + b_c4[it]);
    }

    for (int kc = 0; kc < 16; kc++) {
        // store prefetched chunk to smem (tf32 convert)
#pragma unroll
        for (int it = 0; it < 4; it++) {
            uint4 t;
            t.x = f32_to_tf32(pa[it].x); t.y = f32_to_tf32(pa[it].y);
            t.z = f32_to_tf32(pa[it].z); t.w = f32_to_tf32(pa[it].w);
            *(uint4*)&sA[a_row[it] * A_PITCH + a_c4[it]] = t;
            uint4 u;
            u.x = f32_to_tf32(pb[it].x); u.y = f32_to_tf32(pb[it].y);
            u.z = f32_to_tf32(pb[it].z); u.w = f32_to_tf32(pb[it].w);
            *(uint4*)&sB[b_k[it] * B_PITCH + b_c4[it]] = u;
        }
        __syncthreads();

        // prefetch next chunk (LDGs in flight during compute)
        if (kc < 15) {
            const int k0n = (kc + 1) << 5;
#pragma unroll
            for (int it = 0; it < 4; it++) {
                pa[it] = *(const float4*)(X + (size_t)(m0 + a_row[it]) * 512 + k0n + a_c4[it]);
                pb[it] = *(const float4*)(Wx + (size_t)(k0n + b_k[it]) * 2048 + n0 + b_c4[it]);
            }
        }

#pragma unroll
        for (int k8 = 0; k8 < 4; k8++) {
            const int kb = k8 << 3;
            uint32_t a[2][4];
#pragma unroll
            for (int mf = 0; mf < 2; mf++) {
                int r = wr * 32 + mf * 16 + gid;
                a[mf][0] = sA[r * A_PITCH + kb + tig];
                a[mf][1] = sA[(r + 8) * A_PITCH + kb + tig];
                a[mf][2] = sA[r * A_PITCH + kb + tig + 4];
                a[mf][3] = sA[(r + 8) * A_PITCH + kb + tig + 4];
            }
#pragma unroll
            for (int nf = 0; nf < 8; nf++) {
                int n = wc * 64 + nf * 8 + gid;
                uint32_t b0 = sB[(kb + tig) * B_PITCH + n];
                uint32_t b1 = sB[(kb + tig + 4) * B_PITCH + n];
                mma_tf32(acc[0][nf], a[0][0], a[0][1], a[0][2], a[0][3], b0, b1);
                mma_tf32(acc[1][nf], a[1][0], a[1][1], a[1][2], a[1][3], b0, b1);
            }
        }
        __syncthreads();
    }

    // epilogue -> time-major [t][b][col]
    const int bidx = m0 >> 9;   // batch constant within this 128-row tile
#pragma unroll
    for (int nf = 0; nf < 8; nf++) {
        int col = n0 + wc * 64 + nf * 8 + tig * 2;
        float bv0 = bias[col], bv1 = bias[col + 1];
#pragma unroll
        for (int mf = 0; mf < 2; mf++) {
            int r0 = m0 + wr * 32 + mf * 16 + gid;
            int t0 = r0 & 511;
            float2 lo = make_float2(acc[mf][nf][0] + bv0, acc[mf][nf][1] + bv1);
            float2 hi = make_float2(acc[mf][nf][2] + bv0, acc[mf][nf][3] + bv1);
            *(float2*)&g_xpre[((size_t)t0 * 64 + bidx) * 2048 + col]       = lo;
            *(float2*)&g_xpre[((size_t)(t0 + 8) * 64 + bidx) * 2048 + col] = hi;
        }
    }
}

// -------------------- kernel 2: persistent LSTM recurrence, 2 chains/CTA --------------------
// 64 CTAs = 2 pair-groups x 32 unit-groups. Each CTA runs TWO independent
// 16-batch chains (A/B) interleaved; each chain's barrier + global-h latency
// hides under the other chain's compute. sW (Wh slice, bf16 hi/lo) shared;
// sH/sZ reused sequentially by the two chains.
#define WP  68            // sW pitch (uint2)
#define HPP 260           // sHh/sHl pitch (uint32)
#define SW_BYTES (256 * WP * 8)
#define SH_BYTES (16 * HPP * 4)
#define SMEM_BYTES (SW_BYTES + 2 * SH_BYTES + 1024 * 4)

__global__ __launch_bounds__(256, 1) void lstm_seq4(
    const float* __restrict__ h0g,  // [64, 512]
    const float* __restrict__ c0,   // [64, 512]
    const float* __restrict__ Wh,   // [512, 2048]
    float* __restrict__ out)        // [512, 64, 512]
{
    extern __shared__ char smraw[];
    uint2*    sW  = (uint2*)smraw;                       // [kp 256][c 64] (+pad)
    uint32_t* sHh = (uint32_t*)(smraw + SW_BYTES);       // [row 16][kp 256] (+pad)
    uint32_t* sHl = sHh + 16 * HPP;
    float*    sZ  = (float*)(smraw + SW_BYTES + 2 * SH_BYTES);  // [gate][16b][16u]

    const int tid  = threadIdx.x;
    const int lane = tid & 31;
    const int wid  = tid >> 5;
    const int ug = blockIdx.x & 31;      // unit group
    const int pg = blockIdx.x >> 5;      // pair group (0..1)
    const int u0 = ug << 4;
    const int b0A = pg << 5;             // chain A batches
    const int b0B = b0A + 16;            // chain B batches
    const int idA = pg * 2;              // barrier ids
    const int idB = pg * 2 + 1;

    // ---- one-time: split Wh slice into smem (hi,lo) packed words
    for (int idx = tid; idx < 16384; idx += 256) {
        int kp = idx >> 6;               // 0..255 (pairs of k)
        int c  = idx & 63;               // gate*16 + j
        int gate = c >> 4, j = c & 15;
        int col = gate * 512 + u0 + j;
        float w0 = Wh[(size_t)(2 * kp) * 2048 + col];
        float w1 = Wh[(size_t)(2 * kp + 1) * 2048 + col];
        __nv_bfloat16 h0b = __float2bfloat16_rn(w0);
        __nv_bfloat16 h1b = __float2bfloat16_rn(w1);
        __nv_bfloat16 l0b = __float2bfloat16_rn(w0 - __bfloat162float(h0b));
        __nv_bfloat16 l1b = __float2bfloat16_rn(w1 - __bfloat162float(h1b));
        sW[kp * WP + c] = make_uint2(packbf(h0b, h1b), packbf(l0b, l1b));
    }

    // ---- per-thread cell state + initial h split for both chains
    const int bl = tid >> 4, ul = tid & 15;
    const int gA = (b0A + bl) * 512 + u0 + ul;
    const int gB = (b0B + bl) * 512 + u0 + ul;
    float c_regA = c0[gA];
    float c_regB = c0[gB];
    {
        float hv0 = h0g[gA];
        __nv_bfloat16 hi = __float2bfloat16_rn(hv0);
        g_hh[0][gA] = hi;
        g_hl[0][gA] = __float2bfloat16_rn(hv0 - __bfloat162float(hi));
        float hv1 = h0g[gB];
        __nv_bfloat16 hi1 = __float2bfloat16_rn(hv1);
        g_hh[0][gB] = hi1;
        g_hl[0][gB] = __float2bfloat16_rn(hv1 - __bfloat162float(hi1));
    }

    // ---- GEMM warp constants (wid 0..3, warp = gate)
    const int g  = lane >> 2;            // 0..7
    const int t4 = lane & 3;             // 0..3
    const uint32_t* Ah  = sHh + g * HPP;
    const uint32_t* Ah8 = sHh + (g + 8) * HPP;
    const uint32_t* Al  = sHl + g * HPP;
    const uint32_t* Al8 = sHl + (g + 8) * HPP;
    const uint2* Bw0 = sW + (wid * 16 + g);        // half 0 cols
    const uint2* Bw1 = sW + (wid * 16 + 8 + g);    // half 1 cols

    // ---- publish initial state
    __syncthreads();
    unsigned tgtA = 0, tgtB = 0;         // valid in thread 0 only
    if (tid == 0) {
        __threadfence();
        tgtA = bar_arrive(idA);
        tgtB = bar_arrive(idB);
    }

    for (int tstep = 0; tstep < SEQ; tstep++) {
        const int rb = tstep & 1;

#pragma unroll
        for (int chain = 0; chain < 2; chain++) {
            const int b0c = chain ? b0B : b0A;
            const int idc = chain ? idB : idA;

            // ---- wait for h(t) of this chain
            if (tid == 0) {
                bar_wait(idc, chain ? tgtB : tgtA);
                __threadfence();
            }
            __syncthreads();

            // ---- copy pre-split H tile into smem (pure uint4 copy)
            {
                const uint4* srcHh = (const uint4*)(g_hh[rb] + (size_t)b0c * 512);
                const uint4* srcHl = (const uint4*)(g_hl[rb] + (size_t)b0c * 512);
#pragma unroll
                for (int it = 0; it < 4; it++) {
                    int i = tid + (it << 8);        // 0..1023
                    int row = i >> 6, q = i & 63;
                    *(uint4*)&sHh[row * HPP + q * 4] = srcHh[row * 64 + q];
                    *(uint4*)&sHl[row * HPP + q * 4] = srcHl[row * 64 + q];
                }
            }
            __syncthreads();

            float a00[4] = {0,0,0,0}, a01[4] = {0,0,0,0}, a02[4] = {0,0,0,0};
            float a10[4] = {0,0,0,0}, a11[4] = {0,0,0,0}, a12[4] = {0,0,0,0};

            if (wid < 4) {
                // ---- GEMM: 3-product bf16 split, n=16, full K in regs
#pragma unroll 4
                for (int kb = 0; kb < 32; kb++) {
                    int wa = kb * 8 + t4;
                    uint32_t ah0 = Ah[wa],  ah1 = Ah8[wa];
                    uint32_t ah2 = Ah[wa + 4], ah3 = Ah8[wa + 4];
                    uint32_t al0 = Al[wa],  al1 = Al8[wa];
                    uint32_t al2 = Al[wa + 4], al3 = Al8[wa + 4];
                    uint2 b00 = Bw0[wa * WP], b01 = Bw0[(wa + 4) * WP];
                    uint2 b10 = Bw1[wa * WP], b11 = Bw1[(wa + 4) * WP];
                    mma_bf16(a00, ah0, ah1, ah2, ah3, b00.x, b01.x);
                    mma_bf16(a01, ah0, ah1, ah2, ah3, b00.y, b01.y);
                    mma_bf16(a02, al0, al1, al2, al3, b00.x, b01.x);
                    mma_bf16(a10, ah0, ah1, ah2, ah3, b10.x, b11.x);
                    mma_bf16(a11, ah0, ah1, ah2, ah3, b10.y, b11.y);
                    mma_bf16(a12, al0, al1, al2, al3, b10.x, b11.x);
                }
            } else {
                // ---- warps 4-7: Xpre tile -> sZ (overlapped with GEMM)
                int tl = tid - 128;
                const float* xsrc = g_xpre + ((size_t)tstep * 64 + b0c) * 2048 + u0;
#pragma unroll
                for (int it = 0; it < 8; it++) {
                    int o = tl + (it << 7);          // gate*256 + bb*16 + j
                    int gate = o >> 8, bb = (o >> 4) & 15, j = o & 15;
                    sZ[o] = xsrc[(size_t)bb * 2048 + gate * 512 + j];
                }
            }
            __syncthreads();

            // ---- GEMM warps fold accumulators into sZ
            if (wid < 4) {
                int base0 = wid * 256 + 2 * t4;
                sZ[base0 + g * 16]           += a00[0] + a01[0] + a02[0];
                sZ[base0 + g * 16 + 1]       += a00[1] + a01[1] + a02[1];
                sZ[base0 + (g + 8) * 16]     += a00[2] + a01[2] + a02[2];
                sZ[base0 + (g + 8) * 16 + 1] += a00[3] + a01[3] + a02[3];
                int base1 = base0 + 8;
                sZ[base1 + g * 16]           += a10[0] + a11[0] + a12[0];
                sZ[base1 + g * 16 + 1]       += a10[1] + a11[1] + a12[1];
                sZ[base1 + (g + 8) * 16]     += a10[2] + a11[2] + a12[2];
                sZ[base1 + (g + 8) * 16 + 1] += a10[3] + a11[3] + a12[3];
            }
            __syncthreads();

            // ---- elementwise LSTM cell (Keras gate order i,f,g,o)
            {
                float zi = sZ[tid];
                float zf = sZ[256 + tid];
                float zg = sZ[512 + tid];
                float zo = sZ[768 + tid];
                float ig = sigmoid_f(zi);
                float fg = sigmoid_f(zf);
                float gg = tanh_f(zg);
                float og = sigmoid_f(zo);
                float& c_reg = chain ? c_regB : c_regA;
                c_reg = fg * c_reg + ig * gg;
                float hv = og * tanh_f(c_reg);
                int gidx = chain ? gB : gA;
                __nv_bfloat16 hi = __float2bfloat16_rn(hv);
                g_hh[rb ^ 1][gidx] = hi;
                g_hl[rb ^ 1][gidx] = __float2bfloat16_rn(hv - __bfloat162float(hi));
                out[((size_t)tstep * 64 + b0c + bl) * 512 + u0 + ul] = hv;
            }
            __syncthreads();

            // ---- publish h(t+1): arrive (non-blocking)
            if (tid == 0) {
                __threadfence();
                unsigned nt = bar_arrive(idc);
                if (chain) tgtB = nt; else tgtA = nt;
            }
        }
    }
}

// -------------------- launch --------------------
// Input order (metadata): x [64,512,512], h0 [64,512], c0 [64,512],
//                         Wx [512,2048], Wh [512,2048], b [2048]
extern "C" void kernel_launch(void* const* d_in, const int* in_sizes, int n_in,
                              void* d_out, int out_size) {
    const float* x    = (const float*)d_in[0];
    const float* h0   = (const float*)d_in[1];
    const float* c0   = (const float*)d_in[2];
    const float* Wx   = (const float*)d_in[3];
    const float* Wh   = (const float*)d_in[4];
    const float* bias = (const float*)d_in[5];
    float* out = (float*)d_out;

    cudaFuncSetAttribute(lstm_seq4, cudaFuncAttributeMaxDynamicSharedMemorySize, SMEM_BYTES);

    xpre_mma<<<dim3(16, 256), 256>>>(x, Wx, bias);
    lstm_seq4<<<64, 256, SMEM_BYTES>>>(h0, c0, Wh, out);
}

// round 7
// speedup vs baseline: 1.7489x; 1.7489x over previous
#include <cuda_runtime.h>
#include <cuda_bf16.h>
#include <cstdint>
#include <cstddef>

// Problem constants
#define SEQ    512
#define BATCH  64
#define UNITS  512
#define GATES  2048          // 4*UNITS, Keras order i,f,g,o

// -------------------- device scratch (no cudaMalloc allowed) --------------------
__device__ float g_xpre[(size_t)SEQ * BATCH * GATES];        // [t][b][gate_col]
__device__ __nv_bfloat16 g_hh[2][BATCH * UNITS];             // h hi, double buffered
__device__ __nv_bfloat16 g_hl[2][BATCH * UNITS];             // h lo
__device__ unsigned g_flag[4][32];                           // per-bg line of 32 CTA counters

// -------------------- helpers --------------------
__device__ __forceinline__ uint32_t f32_to_tf32(float x) {
    uint32_t r; asm("cvt.rna.tf32.f32 %0, %1;" : "=r"(r) : "f"(x)); return r;
}

__device__ __forceinline__ void mma_tf32(float c[4],
                                         uint32_t a0, uint32_t a1, uint32_t a2, uint32_t a3,
                                         uint32_t b0, uint32_t b1) {
    asm volatile(
        "mma.sync.aligned.m16n8k8.row.col.f32.tf32.tf32.f32 "
        "{%0,%1,%2,%3}, {%4,%5,%6,%7}, {%8,%9}, {%0,%1,%2,%3};"
        : "+f"(c[0]), "+f"(c[1]), "+f"(c[2]), "+f"(c[3])
        : "r"(a0), "r"(a1), "r"(a2), "r"(a3), "r"(b0), "r"(b1));
}

__device__ __forceinline__ void mma_bf16(float c[4],
                                         uint32_t a0, uint32_t a1, uint32_t a2, uint32_t a3,
                                         uint32_t b0, uint32_t b1) {
    asm volatile(
        "mma.sync.aligned.m16n8k16.row.col.f32.bf16.bf16.f32 "
        "{%0,%1,%2,%3}, {%4,%5,%6,%7}, {%8,%9}, {%0,%1,%2,%3};"
        : "+f"(c[0]), "+f"(c[1]), "+f"(c[2]), "+f"(c[3])
        : "r"(a0), "r"(a1), "r"(a2), "r"(a3), "r"(b0), "r"(b1));
}

__device__ __forceinline__ uint32_t packbf(__nv_bfloat16 lo, __nv_bfloat16 hi) {
    __nv_bfloat162 p = __halves2bfloat162(lo, hi);   // .x = low 16 bits (even k)
    return *(uint32_t*)&p;
}

__device__ __forceinline__ float sigmoid_f(float x) {
    return 1.0f / (1.0f + __expf(-x));
}
__device__ __forceinline__ float tanh_f(float x) {
    float e = __expf(-2.0f * fabsf(x));
    float t = (1.0f - e) / (1.0f + e);
    return copysignf(t, x);
}

// -------------------- kernel 1: Xpre = x @ Wx + bias (mma.sync tf32) --------------------
// Output layout: time-major g_xpre[t][b][col]. Register-prefetch double buffer.
#define A_PITCH 36
#define B_PITCH 136

__global__ __launch_bounds__(256, 2) void xpre_mma(
    const float* __restrict__ X,     // [32768, 512] rows m = b*512 + t
    const float* __restrict__ Wx,    // [512, 2048]
    const float* __restrict__ bias)  // [2048]
{
    __shared__ uint32_t sA[128 * A_PITCH];   // 18 KB
    __shared__ uint32_t sB[32 * B_PITCH];    // 17.4 KB

    const int tid  = threadIdx.x;
    const int lane = tid & 31;
    const int wid  = tid >> 5;
    const int m0 = blockIdx.y << 7;
    const int n0 = blockIdx.x << 7;
    const int wr = wid >> 1;
    const int wc = wid & 1;
    const int gid = lane >> 2;
    const int tig = lane & 3;

    int a_row[4], a_c4[4], b_k[4], b_c4[4];
#pragma unroll
    for (int it = 0; it < 4; it++) {
        int idx = tid + (it << 8);
        a_row[it] = idx >> 3;
        a_c4[it]  = (idx & 7) << 2;
        b_k[it]   = idx >> 5;
        b_c4[it]  = (idx & 31) << 2;
    }

    float acc[2][8][4];
#pragma unroll
    for (int mf = 0; mf < 2; mf++)
#pragma unroll
        for (int nf = 0; nf < 8; nf++)
#pragma unroll
            for (int q = 0; q < 4; q++) acc[mf][nf][q] = 0.0f;

    float4 pa[4], pb[4];
#pragma unroll
    for (int it = 0; it < 4; it++) {
        pa[it] = *(const float4*)(X + (size_t)(m0 + a_row[it]) * 512 + a_c4[it]);
        pb[it] = *(const float4*)(Wx + (size_t)b_k[it] * 2048 + n0 + b_c4[it]);
    }

    for (int kc = 0; kc < 16; kc++) {
#pragma unroll
        for (int it = 0; it < 4; it++) {
            uint4 t;
            t.x = f32_to_tf32(pa[it].x); t.y = f32_to_tf32(pa[it].y);
            t.z = f32_to_tf32(pa[it].z); t.w = f32_to_tf32(pa[it].w);
            *(uint4*)&sA[a_row[it] * A_PITCH + a_c4[it]] = t;
            uint4 u;
            u.x = f32_to_tf32(pb[it].x); u.y = f32_to_tf32(pb[it].y);
            u.z = f32_to_tf32(pb[it].z); u.w = f32_to_tf32(pb[it].w);
            *(uint4*)&sB[b_k[it] * B_PITCH + b_c4[it]] = u;
        }
        __syncthreads();

        if (kc < 15) {
            const int k0n = (kc + 1) << 5;
#pragma unroll
            for (int it = 0; it < 4; it++) {
                pa[it] = *(const float4*)(X + (size_t)(m0 + a_row[it]) * 512 + k0n + a_c4[it]);
                pb[it] = *(const float4*)(Wx + (size_t)(k0n + b_k[it]) * 2048 + n0 + b_c4[it]);
            }
        }

#pragma unroll
        for (int k8 = 0; k8 < 4; k8++) {
            const int kb = k8 << 3;
            uint32_t a[2][4];
#pragma unroll
            for (int mf = 0; mf < 2; mf++) {
                int r = wr * 32 + mf * 16 + gid;
                a[mf][0] = sA[r * A_PITCH + kb + tig];
                a[mf][1] = sA[(r + 8) * A_PITCH + kb + tig];
                a[mf][2] = sA[r * A_PITCH + kb + tig + 4];
                a[mf][3] = sA[(r + 8) * A_PITCH + kb + tig + 4];
            }
#pragma unroll
            for (int nf = 0; nf < 8; nf++) {
                int n = wc * 64 + nf * 8 + gid;
                uint32_t b0 = sB[(kb + tig) * B_PITCH + n];
                uint32_t b1 = sB[(kb + tig + 4) * B_PITCH + n];
                mma_tf32(acc[0][nf], a[0][0], a[0][1], a[0][2], a[0][3], b0, b1);
                mma_tf32(acc[1][nf], a[1][0], a[1][1], a[1][2], a[1][3], b0, b1);
            }
        }
        __syncthreads();
    }

    const int bidx = m0 >> 9;
#pragma unroll
    for (int nf = 0; nf < 8; nf++) {
        int col = n0 + wc * 64 + nf * 8 + tig * 2;
        float bv0 = bias[col], bv1 = bias[col + 1];
#pragma unroll
        for (int mf = 0; mf < 2; mf++) {
            int r0 = m0 + wr * 32 + mf * 16 + gid;
            int t0 = r0 & 511;
            float2 lo = make_float2(acc[mf][nf][0] + bv0, acc[mf][nf][1] + bv1);
            float2 hi = make_float2(acc[mf][nf][2] + bv0, acc[mf][nf][3] + bv1);
            *(float2*)&g_xpre[((size_t)t0 * 64 + bidx) * 2048 + col]       = lo;
            *(float2*)&g_xpre[((size_t)(t0 + 8) * 64 + bidx) * 2048 + col] = hi;
        }
    }
}

// -------------------- kernel 2: persistent LSTM recurrence --------------------
// 128 CTAs = 4 bg (16 batches) x 32 ug (16 units). Flag-array barrier
// (distinct-address atomics + warp-parallel poll), register-prefetched Xpre.
#define WP  68            // sW pitch (uint2)
#define HPP 260           // sHh/sHl pitch (uint32)
#define SW_BYTES (256 * WP * 8)
#define SH_BYTES (16 * HPP * 4)
#define SMEM_BYTES (SW_BYTES + 2 * SH_BYTES + 1024 * 4)

__global__ __launch_bounds__(256, 1) void lstm_seq5(
    const float* __restrict__ h0g,  // [64, 512]
    const float* __restrict__ c0,   // [64, 512]
    const float* __restrict__ Wh,   // [512, 2048]
    float* __restrict__ out)        // [512, 64, 512]
{
    extern __shared__ char smraw[];
    uint2*    sW  = (uint2*)smraw;                       // [kp 256][c 64] (+pad)
    uint32_t* sHh = (uint32_t*)(smraw + SW_BYTES);       // [row 16][kp 256] (+pad)
    uint32_t* sHl = sHh + 16 * HPP;
    float*    sZ  = (float*)(smraw + SW_BYTES + 2 * SH_BYTES);  // [gate][16b][16u]

    const int tid  = threadIdx.x;
    const int lane = tid & 31;
    const int wid  = tid >> 5;
    const int ug = blockIdx.x & 31;      // unit group
    const int bg = blockIdx.x >> 5;      // batch group
    const int u0 = ug << 4;
    const int b0 = bg << 4;

    // ---- one-time: split Wh slice into smem (hi,lo) packed words
    for (int idx = tid; idx < 16384; idx += 256) {
        int kp = idx >> 6;               // 0..255 (pairs of k)
        int c  = idx & 63;               // gate*16 + j
        int gate = c >> 4, j = c & 15;
        int col = gate * 512 + u0 + j;
        float w0 = Wh[(size_t)(2 * kp) * 2048 + col];
        float w1 = Wh[(size_t)(2 * kp + 1) * 2048 + col];
        __nv_bfloat16 h0b = __float2bfloat16_rn(w0);
        __nv_bfloat16 h1b = __float2bfloat16_rn(w1);
        __nv_bfloat16 l0b = __float2bfloat16_rn(w0 - __bfloat162float(h0b));
        __nv_bfloat16 l1b = __float2bfloat16_rn(w1 - __bfloat162float(h1b));
        sW[kp * WP + c] = make_uint2(packbf(h0b, h1b), packbf(l0b, l1b));
    }

    // ---- per-thread cell state + initial h split (own (b,u) element)
    const int bl = tid >> 4, ul = tid & 15;
    const int gidx = (b0 + bl) * 512 + u0 + ul;
    float c_reg = c0[gidx];
    {
        float hv0 = h0g[gidx];
        __nv_bfloat16 hi = __float2bfloat16_rn(hv0);
        g_hh[0][gidx] = hi;
        g_hl[0][gidx] = __float2bfloat16_rn(hv0 - __bfloat162float(hi));
    }

    // ---- GEMM warp constants (wid 0..3, warp = gate)
    const int g  = lane >> 2;            // 0..7
    const int t4 = lane & 3;             // 0..3
    const uint32_t* Ah  = sHh + g * HPP;
    const uint32_t* Ah8 = sHh + (g + 8) * HPP;
    const uint32_t* Al  = sHl + g * HPP;
    const uint32_t* Al8 = sHl + (g + 8) * HPP;
    const uint2* Bw0 = sW + (wid * 16 + g);        // half 0 cols
    const uint2* Bw1 = sW + (wid * 16 + 8 + g);    // half 1 cols

    // ---- Xpre prefetch coordinates (warps 4-7)
    const int tl = tid - 128;
    float xv[8];
    if (wid >= 4) {
        const float* xsrc = g_xpre + (size_t)b0 * 2048 + u0;   // t=0
#pragma unroll
        for (int it = 0; it < 8; it++) {
            int o = tl + (it << 7);
            int gate = o >> 8, bb = (o >> 4) & 15, j = o & 15;
            xv[it] = xsrc[(size_t)bb * 2048 + gate * 512 + j];
        }
    }

    // ---- publish init state
    unsigned myTgt = 0;                  // meaningful in warp 0 only
    __syncthreads();
    if (wid == 0) {
        unsigned n = 0;
        if (lane == 0) { __threadfence(); n = atomicAdd(&g_flag[bg][ug], 1u) + 1u; }
        myTgt = __shfl_sync(0xffffffffu, n, 0);
    }

    for (int tstep = 0; tstep < SEQ; tstep++) {
        const int rb = tstep & 1;

        // ---- WAIT: warp 0 polls the 32 peer flags (one coalesced line)
        if (wid == 0) {
            for (;;) {
                unsigned v = *(volatile unsigned*)&g_flag[bg][lane];
                if (__all_sync(0xffffffffu, (int)(v - myTgt) >= 0)) break;
            }
            if (lane == 0) __threadfence();
        }
        __syncthreads();

        // ---- PHASE 1: copy pre-split H tile into smem (all 8 warps)
        {
            const uint4* srcHh = (const uint4*)(g_hh[rb] + (size_t)b0 * 512);
            const uint4* srcHl = (const uint4*)(g_hl[rb] + (size_t)b0 * 512);
#pragma unroll
            for (int it = 0; it < 4; it++) {
                int i = tid + (it << 8);        // 0..1023
                int row = i >> 6, q = i & 63;
                *(uint4*)&sHh[row * HPP + q * 4] = srcHh[row * 64 + q];
                *(uint4*)&sHl[row * HPP + q * 4] = srcHl[row * 64 + q];
            }
        }
        // warps 4-7: prefetched Xpre -> sZ, then prefetch next step's tile
        if (wid >= 4) {
#pragma unroll
            for (int it = 0; it < 8; it++) {
                int o = tl + (it << 7);
                sZ[o] = xv[it];
            }
            if (tstep + 1 < SEQ) {
                const float* xsrc = g_xpre + ((size_t)(tstep + 1) * 64 + b0) * 2048 + u0;
#pragma unroll
                for (int it = 0; it < 8; it++) {
                    int o = tl + (it << 7);
                    int gate = o >> 8, bb = (o >> 4) & 15, j = o & 15;
                    xv[it] = xsrc[(size_t)bb * 2048 + gate * 512 + j];
                }
            }
        }
        __syncthreads();

        // ---- PHASE 2: warps 0-3: GEMM (bf16 3-term split, full K) + fold
        if (wid < 4) {
            float a00[4] = {0,0,0,0}, a01[4] = {0,0,0,0}, a02[4] = {0,0,0,0};
            float a10[4] = {0,0,0,0}, a11[4] = {0,0,0,0}, a12[4] = {0,0,0,0};
#pragma unroll 4
            for (int kb = 0; kb < 32; kb++) {
                int wa = kb * 8 + t4;
                uint32_t ah0 = Ah[wa],  ah1 = Ah8[wa];
                uint32_t ah2 = Ah[wa + 4], ah3 = Ah8[wa + 4];
                uint32_t al0 = Al[wa],  al1 = Al8[wa];
                uint32_t al2 = Al[wa + 4], al3 = Al8[wa + 4];
                uint2 b00 = Bw0[wa * WP], b01 = Bw0[(wa + 4) * WP];
                uint2 b10 = Bw1[wa * WP], b11 = Bw1[(wa + 4) * WP];
                mma_bf16(a00, ah0, ah1, ah2, ah3, b00.x, b01.x);
                mma_bf16(a01, ah0, ah1, ah2, ah3, b00.y, b01.y);
                mma_bf16(a02, al0, al1, al2, al3, b00.x, b01.x);
                mma_bf16(a10, ah0, ah1, ah2, ah3, b10.x, b11.x);
                mma_bf16(a11, ah0, ah1, ah2, ah3, b10.y, b11.y);
                mma_bf16(a12, al0, al1, al2, al3, b10.x, b11.x);
            }
            int base0 = wid * 256 + 2 * t4;
            sZ[base0 + g * 16]           += a00[0] + a01[0] + a02[0];
            sZ[base0 + g * 16 + 1]       += a00[1] + a01[1] + a02[1];
            sZ[base0 + (g + 8) * 16]     += a00[2] + a01[2] + a02[2];
            sZ[base0 + (g + 8) * 16 + 1] += a00[3] + a01[3] + a02[3];
            int base1 = base0 + 8;
            sZ[base1 + g * 16]           += a10[0] + a11[0] + a12[0];
            sZ[base1 + g * 16 + 1]       += a10[1] + a11[1] + a12[1];
            sZ[base1 + (g + 8) * 16]     += a10[2] + a11[2] + a12[2];
            sZ[base1 + (g + 8) * 16 + 1] += a10[3] + a11[3] + a12[3];
        }
        __syncthreads();

        // ---- PHASE 3: elementwise LSTM cell (Keras gate order i,f,g,o)
        float hv;
        {
            float zi = sZ[tid];
            float zf = sZ[256 + tid];
            float zg = sZ[512 + tid];
            float zo = sZ[768 + tid];
            float ig = sigmoid_f(zi);
            float fg = sigmoid_f(zf);
            float gg = tanh_f(zg);
            float og = sigmoid_f(zo);
            c_reg = fg * c_reg + ig * gg;
            hv = og * tanh_f(c_reg);
            __nv_bfloat16 hi = __float2bfloat16_rn(hv);
            g_hh[rb ^ 1][gidx] = hi;
            g_hl[rb ^ 1][gidx] = __float2bfloat16_rn(hv - __bfloat162float(hi));
        }
        __syncthreads();

        // ---- ARRIVE (fire-and-forget), then out store off the critical path
        if (wid == 0) {
            unsigned n = 0;
            if (lane == 0) { __threadfence(); n = atomicAdd(&g_flag[bg][ug], 1u) + 1u; }
            myTgt = __shfl_sync(0xffffffffu, n, 0);
        }
        out[((size_t)tstep * 64 + b0 + bl) * 512 + u0 + ul] = hv;
    }
}

// -------------------- launch --------------------
// Input order (metadata): x [64,512,512], h0 [64,512], c0 [64,512],
//                         Wx [512,2048], Wh [512,2048], b [2048]
extern "C" void kernel_launch(void* const* d_in, const int* in_sizes, int n_in,
                              void* d_out, int out_size) {
    const float* x    = (const float*)d_in[0];
    const float* h0   = (const float*)d_in[1];
    const float* c0   = (const float*)d_in[2];
    const float* Wx   = (const float*)d_in[3];
    const float* Wh   = (const float*)d_in[4];
    const float* bias = (const float*)d_in[5];
    float* out = (float*)d_out;

    cudaFuncSetAttribute(lstm_seq5, cudaFuncAttributeMaxDynamicSharedMemorySize, SMEM_BYTES);

    xpre_mma<<<dim3(16, 256), 256>>>(x, Wx, bias);
    lstm_seq5<<<128, 256, SMEM_BYTES>>>(h0, c0, Wh, out);
}

// round 8
// speedup vs baseline: 1.9701x; 1.1264x over previous
#include <cuda_runtime.h>
#include <cuda_bf16.h>
#include <cstdint>
#include <cstddef>

// Problem constants
#define SEQ    512
#define BATCH  64
#define UNITS  512
#define GATES  2048          // 4*UNITS, Keras order i,f,g,o

// -------------------- device scratch (no cudaMalloc allowed) --------------------
__device__ float g_xpre[(size_t)SEQ * BATCH * GATES];        // [t][b][gate_col]
__device__ __nv_bfloat16 g_hh[2][BATCH * UNITS];             // h hi, double buffered
__device__ __nv_bfloat16 g_hl[2][BATCH * UNITS];             // h lo
__device__ unsigned g_flag[4][32];                           // per-bg line of 32 CTA counters

// -------------------- helpers --------------------
__device__ __forceinline__ uint32_t f32_to_tf32(float x) {
    uint32_t r; asm("cvt.rna.tf32.f32 %0, %1;" : "=r"(r) : "f"(x)); return r;
}

__device__ __forceinline__ void mma_tf32(float c[4],
                                         uint32_t a0, uint32_t a1, uint32_t a2, uint32_t a3,
                                         uint32_t b0, uint32_t b1) {
    asm volatile(
        "mma.sync.aligned.m16n8k8.row.col.f32.tf32.tf32.f32 "
        "{%0,%1,%2,%3}, {%4,%5,%6,%7}, {%8,%9}, {%0,%1,%2,%3};"
        : "+f"(c[0]), "+f"(c[1]), "+f"(c[2]), "+f"(c[3])
        : "r"(a0), "r"(a1), "r"(a2), "r"(a3), "r"(b0), "r"(b1));
}

__device__ __forceinline__ void mma_bf16(float c[4],
                                         uint32_t a0, uint32_t a1, uint32_t a2, uint32_t a3,
                                         uint32_t b0, uint32_t b1) {
    asm volatile(
        "mma.sync.aligned.m16n8k16.row.col.f32.bf16.bf16.f32 "
        "{%0,%1,%2,%3}, {%4,%5,%6,%7}, {%8,%9}, {%0,%1,%2,%3};"
        : "+f"(c[0]), "+f"(c[1]), "+f"(c[2]), "+f"(c[3])
        : "r"(a0), "r"(a1), "r"(a2), "r"(a3), "r"(b0), "r"(b1));
}

__device__ __forceinline__ uint32_t packbf(__nv_bfloat16 lo, __nv_bfloat16 hi) {
    __nv_bfloat162 p = __halves2bfloat162(lo, hi);   // .x = low 16 bits (even k)
    return *(uint32_t*)&p;
}

__device__ __forceinline__ float sigmoid_f(float x) {
    return 1.0f / (1.0f + __expf(-x));
}
__device__ __forceinline__ float tanh_f(float x) {
    float e = __expf(-2.0f * fabsf(x));
    float t = (1.0f - e) / (1.0f + e);
    return copysignf(t, x);
}

// -------------------- kernel 1: Xpre = x @ Wx + bias (mma.sync tf32) --------------------
// Output layout: time-major g_xpre[t][b][col]. Register-prefetch double buffer.
#define A_PITCH 36
#define B_PITCH 136

__global__ __launch_bounds__(256, 2) void xpre_mma(
    const float* __restrict__ X,     // [32768, 512] rows m = b*512 + t
    const float* __restrict__ Wx,    // [512, 2048]
    const float* __restrict__ bias)  // [2048]
{
    __shared__ uint32_t sA[128 * A_PITCH];   // 18 KB
    __shared__ uint32_t sB[32 * B_PITCH];    // 17.4 KB

    const int tid  = threadIdx.x;
    const int lane = tid & 31;
    const int wid  = tid >> 5;
    const int m0 = blockIdx.y << 7;
    const int n0 = blockIdx.x << 7;
    const int wr = wid >> 1;
    const int wc = wid & 1;
    const int gid = lane >> 2;
    const int tig = lane & 3;

    int a_row[4], a_c4[4], b_k[4], b_c4[4];
#pragma unroll
    for (int it = 0; it < 4; it++) {
        int idx = tid + (it << 8);
        a_row[it] = idx >> 3;
        a_c4[it]  = (idx & 7) << 2;
        b_k[it]   = idx >> 5;
        b_c4[it]  = (idx & 31) << 2;
    }

    float acc[2][8][4];
#pragma unroll
    for (int mf = 0; mf < 2; mf++)
#pragma unroll
        for (int nf = 0; nf < 8; nf++)
#pragma unroll
            for (int q = 0; q < 4; q++) acc[mf][nf][q] = 0.0f;

    float4 pa[4], pb[4];
#pragma unroll
    for (int it = 0; it < 4; it++) {
        pa[it] = *(const float4*)(X + (size_t)(m0 + a_row[it]) * 512 + a_c4[it]);
        pb[it] = *(const float4*)(Wx + (size_t)b_k[it] * 2048 + n0 + b_c4[it]);
    }

    for (int kc = 0; kc < 16; kc++) {
#pragma unroll
        for (int it = 0; it < 4; it++) {
            uint4 t;
            t.x = f32_to_tf32(pa[it].x); t.y = f32_to_tf32(pa[it].y);
            t.z = f32_to_tf32(pa[it].z); t.w = f32_to_tf32(pa[it].w);
            *(uint4*)&sA[a_row[it] * A_PITCH + a_c4[it]] = t;
            uint4 u;
            u.x = f32_to_tf32(pb[it].x); u.y = f32_to_tf32(pb[it].y);
            u.z = f32_to_tf32(pb[it].z); u.w = f32_to_tf32(pb[it].w);
            *(uint4*)&sB[b_k[it] * B_PITCH + b_c4[it]] = u;
        }
        __syncthreads();

        if (kc < 15) {
            const int k0n = (kc + 1) << 5;
#pragma unroll
            for (int it = 0; it < 4; it++) {
                pa[it] = *(const float4*)(X + (size_t)(m0 + a_row[it]) * 512 + k0n + a_c4[it]);
                pb[it] = *(const float4*)(Wx + (size_t)(k0n + b_k[it]) * 2048 + n0 + b_c4[it]);
            }
        }

#pragma unroll
        for (int k8 = 0; k8 < 4; k8++) {
            const int kb = k8 << 3;
            uint32_t a[2][4];
#pragma unroll
            for (int mf = 0; mf < 2; mf++) {
                int r = wr * 32 + mf * 16 + gid;
                a[mf][0] = sA[r * A_PITCH + kb + tig];
                a[mf][1] = sA[(r + 8) * A_PITCH + kb + tig];
                a[mf][2] = sA[r * A_PITCH + kb + tig + 4];
                a[mf][3] = sA[(r + 8) * A_PITCH + kb + tig + 4];
            }
#pragma unroll
            for (int nf = 0; nf < 8; nf++) {
                int n = wc * 64 + nf * 8 + gid;
                uint32_t b0 = sB[(kb + tig) * B_PITCH + n];
                uint32_t b1 = sB[(kb + tig + 4) * B_PITCH + n];
                mma_tf32(acc[0][nf], a[0][0], a[0][1], a[0][2], a[0][3], b0, b1);
                mma_tf32(acc[1][nf], a[1][0], a[1][1], a[1][2], a[1][3], b0, b1);
            }
        }
        __syncthreads();
    }

    const int bidx = m0 >> 9;
#pragma unroll
    for (int nf = 0; nf < 8; nf++) {
        int col = n0 + wc * 64 + nf * 8 + tig * 2;
        float bv0 = bias[col], bv1 = bias[col + 1];
#pragma unroll
        for (int mf = 0; mf < 2; mf++) {
            int r0 = m0 + wr * 32 + mf * 16 + gid;
            int t0 = r0 & 511;
            float2 lo = make_float2(acc[mf][nf][0] + bv0, acc[mf][nf][1] + bv1);
            float2 hi = make_float2(acc[mf][nf][2] + bv0, acc[mf][nf][3] + bv1);
            *(float2*)&g_xpre[((size_t)t0 * 64 + bidx) * 2048 + col]       = lo;
            *(float2*)&g_xpre[((size_t)(t0 + 8) * 64 + bidx) * 2048 + col] = hi;
        }
    }
}

// -------------------- kernel 2: persistent LSTM recurrence --------------------
// 128 CTAs = 4 bg (16 batches) x 32 ug (16 units).
// 8-warp K-split GEMM: warp w -> gate (w&3), K-half (w>>2) of 256 k's.
// Raw partials into sZp[2][1024]; elementwise sums both + per-thread
// register-prefetched Xpre. Release-atomic arrive, acquire-load poll.
#define WP  68            // sW pitch (uint2)
#define HPP 260           // sHh/sHl pitch (uint32)
#define SW_BYTES (256 * WP * 8)
#define SH_BYTES (16 * HPP * 4)
#define SMEM_BYTES (SW_BYTES + 2 * SH_BYTES + 2 * 1024 * 4)

__global__ __launch_bounds__(256, 1) void lstm_seq6(
    const float* __restrict__ h0g,  // [64, 512]
    const float* __restrict__ c0,   // [64, 512]
    const float* __restrict__ Wh,   // [512, 2048]
    float* __restrict__ out)        // [512, 64, 512]
{
    extern __shared__ char smraw[];
    uint2*    sW  = (uint2*)smraw;                       // [kp 256][c 64] (+pad)
    uint32_t* sHh = (uint32_t*)(smraw + SW_BYTES);       // [row 16][kp 256] (+pad)
    uint32_t* sHl = sHh + 16 * HPP;
    float*    sZp = (float*)(smraw + SW_BYTES + 2 * SH_BYTES);  // [2][gate][16b][16u]

    const int tid  = threadIdx.x;
    const int lane = tid & 31;
    const int wid  = tid >> 5;
    const int ug = blockIdx.x & 31;      // unit group
    const int bg = blockIdx.x >> 5;      // batch group
    const int u0 = ug << 4;
    const int b0 = bg << 4;

    // ---- one-time: split Wh slice into smem (hi,lo) packed words
    for (int idx = tid; idx < 16384; idx += 256) {
        int kp = idx >> 6;               // 0..255 (pairs of k)
        int c  = idx & 63;               // gate*16 + j
        int gate = c >> 4, j = c & 15;
        int col = gate * 512 + u0 + j;
        float w0 = Wh[(size_t)(2 * kp) * 2048 + col];
        float w1 = Wh[(size_t)(2 * kp + 1) * 2048 + col];
        __nv_bfloat16 h0b = __float2bfloat16_rn(w0);
        __nv_bfloat16 h1b = __float2bfloat16_rn(w1);
        __nv_bfloat16 l0b = __float2bfloat16_rn(w0 - __bfloat162float(h0b));
        __nv_bfloat16 l1b = __float2bfloat16_rn(w1 - __bfloat162float(h1b));
        sW[kp * WP + c] = make_uint2(packbf(h0b, h1b), packbf(l0b, l1b));
    }

    // ---- per-thread cell state + initial h split (own (b,u) element)
    const int bl = tid >> 4, ul = tid & 15;
    const int gidx = (b0 + bl) * 512 + u0 + ul;
    float c_reg = c0[gidx];
    {
        float hv0 = h0g[gidx];
        __nv_bfloat16 hi = __float2bfloat16_rn(hv0);
        g_hh[0][gidx] = hi;
        g_hl[0][gidx] = __float2bfloat16_rn(hv0 - __bfloat162float(hi));
    }

    // ---- warp roles: gate = wid&3, K-half = wid>>2
    const int gate_w = wid & 3;
    const int kh = wid >> 2;
    const int g  = lane >> 2;            // 0..7
    const int t4 = lane & 3;             // 0..3
    const int kpBase = kh * 128;         // k-pair offset of this warp's half
    const uint32_t* Ah  = sHh + g * HPP + kpBase;
    const uint32_t* Ah8 = sHh + (g + 8) * HPP + kpBase;
    const uint32_t* Al  = sHl + g * HPP + kpBase;
    const uint32_t* Al8 = sHl + (g + 8) * HPP + kpBase;
    const uint2* Bw0 = sW + (size_t)kpBase * WP + (gate_w * 16 + g);
    const uint2* Bw1 = Bw0 + 8;
    float* sZme = sZp + kh * 1024;

    // ---- per-thread Xpre prefetch (4 gate values for own (b,u)), t=0
    const float* xbase = g_xpre + (size_t)(b0 + bl) * 2048 + u0 + ul;
    float xv0 = xbase[0];
    float xv1 = xbase[512];
    float xv2 = xbase[1024];
    float xv3 = xbase[1536];

    // ---- publish init state (release atomic; replay-safe monotonic counters)
    unsigned myTgt = 0;                  // meaningful in warp 0 only
    __syncthreads();
    if (wid == 0 && lane == 0) {
        unsigned n;
        asm volatile("atom.release.gpu.global.add.u32 %0, [%1], %2;"
                     : "=r"(n) : "l"(&g_flag[bg][ug]), "r"(1u) : "memory");
    }
    if (wid == 0) myTgt = 1;             // targets are deterministic relative to entry
    // read entry base AFTER our own arrive would race; instead derive target from
    // polled values: all flags were equal at launch, each CTA adds 1 per phase.
    // Use relative comparison against our OWN flag progression:
    unsigned myCount = 1;                // our arrivals so far

    for (int tstep = 0; tstep < SEQ; tstep++) {
        const int rb = tstep & 1;

        // ---- WAIT: warp 0 polls 32 peer flags; all must have >= myCount arrivals.
        // Flags are monotonic; at entry all equal F0 (unknown). Our own flag =
        // F0 + myCount. Peers needed: >= F0 + myCount, i.e. >= own flag value.
        if (wid == 0) {
            unsigned own;
            asm volatile("ld.acquire.gpu.global.u32 %0, [%1];"
                         : "=r"(own) : "l"(&g_flag[bg][ug]) : "memory");
            for (;;) {
                unsigned v;
                asm volatile("ld.acquire.gpu.global.u32 %0, [%1];"
                             : "=r"(v) : "l"(&g_flag[bg][lane]) : "memory");
                if (__all_sync(0xffffffffu, (int)(v - own) >= 0)) break;
            }
        }
        __syncthreads();

        // ---- PHASE 1: copy pre-split H tile into smem (all 8 warps)
        {
            const uint4* srcHh = (const uint4*)(g_hh[rb] + (size_t)b0 * 512);
            const uint4* srcHl = (const uint4*)(g_hl[rb] + (size_t)b0 * 512);
#pragma unroll
            for (int it = 0; it < 4; it++) {
                int i = tid + (it << 8);        // 0..1023
                int row = i >> 6, q = i & 63;
                *(uint4*)&sHh[row * HPP + q * 4] = srcHh[row * 64 + q];
                *(uint4*)&sHl[row * HPP + q * 4] = srcHl[row * 64 + q];
            }
        }
        __syncthreads();

        // ---- PHASE 2: all 8 warps GEMM their K half (bf16 3-term split)
        {
            float a00[4] = {0,0,0,0}, a01[4] = {0,0,0,0}, a02[4] = {0,0,0,0};
            float a10[4] = {0,0,0,0}, a11[4] = {0,0,0,0}, a12[4] = {0,0,0,0};
#pragma unroll 4
            for (int kb = 0; kb < 16; kb++) {
                int wa = kb * 8 + t4;
                uint32_t ah0 = Ah[wa],  ah1 = Ah8[wa];
                uint32_t ah2 = Ah[wa + 4], ah3 = Ah8[wa + 4];
                uint32_t al0 = Al[wa],  al1 = Al8[wa];
                uint32_t al2 = Al[wa + 4], al3 = Al8[wa + 4];
                uint2 b00 = Bw0[(size_t)wa * WP], b01 = Bw0[(size_t)(wa + 4) * WP];
                uint2 b10 = Bw1[(size_t)wa * WP], b11 = Bw1[(size_t)(wa + 4) * WP];
                mma_bf16(a00, ah0, ah1, ah2, ah3, b00.x, b01.x);
                mma_bf16(a01, ah0, ah1, ah2, ah3, b00.y, b01.y);
                mma_bf16(a02, al0, al1, al2, al3, b00.x, b01.x);
                mma_bf16(a10, ah0, ah1, ah2, ah3, b10.x, b11.x);
                mma_bf16(a11, ah0, ah1, ah2, ah3, b10.y, b11.y);
                mma_bf16(a12, al0, al1, al2, al3, b10.x, b11.x);
            }
            // raw partial stores (disjoint per warp within its sZp bank)
            int base0 = gate_w * 256 + 2 * t4;
            sZme[base0 + g * 16]           = a00[0] + a01[0] + a02[0];
            sZme[base0 + g * 16 + 1]       = a00[1] + a01[1] + a02[1];
            sZme[base0 + (g + 8) * 16]     = a00[2] + a01[2] + a02[2];
            sZme[base0 + (g + 8) * 16 + 1] = a00[3] + a01[3] + a02[3];
            int base1 = base0 + 8;
            sZme[base1 + g * 16]           = a10[0] + a11[0] + a12[0];
            sZme[base1 + g * 16 + 1]       = a10[1] + a11[1] + a12[1];
            sZme[base1 + (g + 8) * 16]     = a10[2] + a11[2] + a12[2];
            sZme[base1 + (g + 8) * 16 + 1] = a10[3] + a11[3] + a12[3];
        }
        __syncthreads();

        // ---- PHASE 3: elementwise LSTM cell (Keras gate order i,f,g,o)
        float hv;
        {
            int o = bl * 16 + ul;
            float zi = sZp[o]        + sZp[1024 + o]        + xv0;
            float zf = sZp[256 + o]  + sZp[1024 + 256 + o]  + xv1;
            float zg = sZp[512 + o]  + sZp[1024 + 512 + o]  + xv2;
            float zo = sZp[768 + o]  + sZp[1024 + 768 + o]  + xv3;
            float ig = sigmoid_f(zi);
            float fg = sigmoid_f(zf);
            float gg = tanh_f(zg);
            float og = sigmoid_f(zo);
            c_reg = fg * c_reg + ig * gg;
            hv = og * tanh_f(c_reg);
            __nv_bfloat16 hi = __float2bfloat16_rn(hv);
            g_hh[rb ^ 1][gidx] = hi;
            g_hl[rb ^ 1][gidx] = __float2bfloat16_rn(hv - __bfloat162float(hi));
        }
        // prefetch next step's Xpre (independent of everything above)
        if (tstep + 1 < SEQ) {
            const float* xnext = xbase + (size_t)(tstep + 1) * 64 * 2048;
            xv0 = xnext[0];
            xv1 = xnext[512];
            xv2 = xnext[1024];
            xv3 = xnext[1536];
        }
        __syncthreads();

        // ---- ARRIVE (release atomic), then out store off the critical path
        if (wid == 0 && lane == 0) {
            unsigned n;
            asm volatile("atom.release.gpu.global.add.u32 %0, [%1], %2;"
                         : "=r"(n) : "l"(&g_flag[bg][ug]), "r"(1u) : "memory");
        }
        myCount++;
        out[((size_t)tstep * 64 + b0 + bl) * 512 + u0 + ul] = hv;
    }
}

// -------------------- launch --------------------
// Input order (metadata): x [64,512,512], h0 [64,512], c0 [64,512],
//                         Wx [512,2048], Wh [512,2048], b [2048]
extern "C" void kernel_launch(void* const* d_in, const int* in_sizes, int n_in,
                              void* d_out, int out_size) {
    const float* x    = (const float*)d_in[0];
    const float* h0   = (const float*)d_in[1];
    const float* c0   = (const float*)d_in[2];
    const float* Wx   = (const float*)d_in[3];
    const float* Wh   = (const float*)d_in[4];
    const float* bias = (const float*)d_in[5];
    float* out = (float*)d_out;

    cudaFuncSetAttribute(lstm_seq6, cudaFuncAttributeMaxDynamicSharedMemorySize, SMEM_BYTES);

    xpre_mma<<<dim3(16, 256), 256>>>(x, Wx, bias);
    lstm_seq6<<<128, 256, SMEM_BYTES>>>(h0, c0, Wh, out);
}